// round 15
// baseline (speedup 1.0000x reference)
#include <cuda_runtime.h>
#include <cuda_bf16.h>
#include <cstdint>

// Problem constants (fixed by the reference)
#define M_ITEMS 20001      // emb rows / segments
#define EDIM    128
#define NE      640000     // edges (divisible by 256)
#define TILE_M  64         // rows per CTA in the MMA GEMM

typedef unsigned long long ull;

// Scratch (device globals: no runtime allocation allowed)
__device__ __nv_bfloat16 g_itemh[M_ITEMS * EDIM]; // item_scaled in bf16 (gather table)
__device__ float g_a1[M_ITEMS];            // item_scaled . W_att[:128]
__device__ float g_a2[M_ITEMS];            // item_scaled . W_att[128:]
__device__ int2  g_ds[NE];                 // packed (dst, score_bits) per edge
__device__ int   g_segstart[M_ITEMS + 1];  // segment boundaries (edges sorted by src)
__device__ alignas(16) unsigned char g_wbf[32768]; // W as pre-swizzled bf16 smem image

// ---------------- warp-MMA helpers (sm_80-class PTX: valid on sm_103) ------
__device__ __forceinline__ uint32_t smem_u32(const void* p) {
    uint32_t a;
    asm("{ .reg .u64 t; cvta.to.shared.u64 t, %1; cvt.u32.u64 %0, t; }" : "=r"(a) : "l"(p));
    return a;
}
// swizzle: XOR row bits (8..10) into the 16B-chunk selector (bits 4..6).
__device__ __forceinline__ uint32_t swz(uint32_t off) {
    return off ^ (((off >> 8) & 7u) << 4);
}
__device__ __forceinline__ void ldsm_x4(uint32_t* r, uint32_t addr) {
    asm volatile("ldmatrix.sync.aligned.m8n8.x4.shared.b16 {%0,%1,%2,%3}, [%4];"
                 : "=r"(r[0]), "=r"(r[1]), "=r"(r[2]), "=r"(r[3]) : "r"(addr));
}
__device__ __forceinline__ void ldsm_x4_t(uint32_t* r, uint32_t addr) {
    asm volatile("ldmatrix.sync.aligned.m8n8.x4.trans.shared.b16 {%0,%1,%2,%3}, [%4];"
                 : "=r"(r[0]), "=r"(r[1]), "=r"(r[2]), "=r"(r[3]) : "r"(addr));
}
__device__ __forceinline__ void mma_bf16(float* c, const uint32_t* a, uint32_t b0, uint32_t b1) {
    asm volatile("mma.sync.aligned.m16n8k16.row.col.f32.bf16.bf16.f32 "
                 "{%0,%1,%2,%3}, {%4,%5,%6,%7}, {%8,%9}, {%0,%1,%2,%3};"
                 : "+f"(c[0]), "+f"(c[1]), "+f"(c[2]), "+f"(c[3])
                 : "r"(a[0]), "r"(a[1]), "r"(a[2]), "r"(a[3]), "r"(b0), "r"(b1));
}
// packed fp32x2 FMA (Blackwell FFMA2; exact per-lane fp32 semantics)
__device__ __forceinline__ void fma2(ull& d, ull a, ull b) {
    asm("fma.rn.f32x2 %0, %1, %2, %0;" : "+l"(d) : "l"(a), "l"(b));
}
__device__ __forceinline__ ull pk2(float lo, float hi) {
    ull r; asm("mov.b64 %0, {%1, %2};" : "=l"(r) : "f"(lo), "f"(hi)); return r;
}
__device__ __forceinline__ void upk2(ull v, float& lo, float& hi) {
    asm("mov.b64 {%0, %1}, %2;" : "=f"(lo), "=f"(hi) : "l"(v));
}
__device__ __forceinline__ void cp_async16(uint32_t smem_dst, const void* gsrc) {
    asm volatile("cp.async.cg.shared.global [%0], [%1], 16;" :: "r"(smem_dst), "l"(gsrc));
}

// Dynamic smem layout: [0,512) bias, [512,1536) Watt, [1536,2560) a1/a2
// reduce buffer, [4096,20480) sA bf16 [64 rows x 256B], [20480,53248) sB.
#define SM_BIAS  0
#define SM_WATT  512
#define SM_RED   1536
#define SM_A     4096
#define SM_B     (4096 + 16384)
#define SM_TOTAL (4096 + 16384 + 32768)

// ---------------------------------------------------------------------------
// K0: one-time W -> pre-swizzled bf16 image (exact smem B layout).
// ---------------------------------------------------------------------------
__global__ void __launch_bounds__(128) k_prep(const float* __restrict__ W) {
    const int idx = blockIdx.x * 128 + threadIdx.x;   // 0..1023
#pragma unroll
    for (int i = 0; i < 4; ++i) {
        const int g   = idx + i * 1024;               // 0..4095 float4 groups
        const int row = g >> 5;                       // k row 0..127
        const int cg  = g & 31;
        const float4 v = reinterpret_cast<const float4*>(W)[(size_t)row * 32 + cg];
        const __nv_bfloat162 h0 = __float22bfloat162_rn(make_float2(v.x, v.y));
        const __nv_bfloat162 h1 = __float22bfloat162_rn(make_float2(v.z, v.w));
        uint2 pk;
        pk.x = *reinterpret_cast<const uint32_t*>(&h0);
        pk.y = *reinterpret_cast<const uint32_t*>(&h1);
        *reinterpret_cast<uint2*>(g_wbf + swz(row * 256 + cg * 8)) = pk;
    }
}

// ---------------------------------------------------------------------------
// K1: item_scaled = emb @ W + b via warp-level bf16 HMMA (fp32 accumulate).
// CTA = 64 rows, 256 threads (8 warps): warp w = (row-group w>>1, N-half w&1),
// 16 rows x 64 cols each. B tile arrives via raw cp.async of the pre-swizzled
// image (no CVT). a1/a2: per-warp quad-reduce -> smem -> fixed-order combine.
// ---------------------------------------------------------------------------
__global__ void __launch_bounds__(256) k_gemm(const float* __restrict__ A,
                                              const float* __restrict__ bias,
                                              const float* __restrict__ Watt) {
    extern __shared__ unsigned char smem_raw[];
    const uint32_t sb = smem_u32(smem_raw);
    float* s_bias = reinterpret_cast<float*>(smem_raw + SM_BIAS);
    float* s_watt = reinterpret_cast<float*>(smem_raw + SM_WATT);
    float* s_red  = reinterpret_cast<float*>(smem_raw + SM_RED);   // [64][4]

    const int tid  = threadIdx.x;
    const int w    = tid >> 5;
    const int lane = tid & 31;
    const int rg   = w >> 1;        // row group 0..3 (16 rows)
    const int nh   = w & 1;         // N half 0/1 (64 cols)
    const int r0   = blockIdx.x * TILE_M;

    // B tile: 2048 x 16B raw async copies (pre-swizzled bf16), issued first.
#pragma unroll
    for (int i = 0; i < 8; ++i) {
        const uint32_t off = (uint32_t)(tid + i * 256) * 16;
        cp_async16(sb + SM_B + off, g_wbf + off);
    }
    asm volatile("cp.async.commit_group;" ::: "memory");

    if (tid < 128) s_bias[tid] = bias[tid];
    s_watt[tid] = Watt[tid];

    // fill sA (A rows r0..r0+63 -> bf16): 2048 float4 groups over 256 threads
#pragma unroll
    for (int i = 0; i < 8; ++i) {
        const int idx = tid + i * 256;
        const int row = idx >> 5;             // 0..63
        const int cg  = idx & 31;
        const int gr  = min(r0 + row, M_ITEMS - 1);
        const float4 v = reinterpret_cast<const float4*>(A)[(size_t)gr * 32 + cg];
        const __nv_bfloat162 h0 = __float22bfloat162_rn(make_float2(v.x, v.y));
        const __nv_bfloat162 h1 = __float22bfloat162_rn(make_float2(v.z, v.w));
        uint2 pk;
        pk.x = *reinterpret_cast<const uint32_t*>(&h0);
        pk.y = *reinterpret_cast<const uint32_t*>(&h1);
        *reinterpret_cast<uint2*>(smem_raw + SM_A + swz(row * 256 + cg * 8)) = pk;
    }
    asm volatile("cp.async.wait_group 0;" ::: "memory");
    __syncthreads();

    // accumulators: 8 n-frags x 4 fp32 (this warp's 64-col half)
    float acc[8][4];
#pragma unroll
    for (int nf = 0; nf < 8; ++nf)
#pragma unroll
        for (int c = 0; c < 4; ++c) acc[nf][c] = 0.f;

    const uint32_t a_row  = (uint32_t)(rg * 16 + (lane & 7) + ((lane >> 3) & 1) * 8);
    const uint32_t a_colh = (uint32_t)((lane >> 4) & 1) * 16;
    const uint32_t b_krow = (uint32_t)(lane & 15);
    const uint32_t b_half = (uint32_t)((lane >> 4) & 1) * 16;

#pragma unroll
    for (int kk = 0; kk < 8; ++kk) {
        uint32_t a[4];
        ldsm_x4(a, sb + SM_A + swz(a_row * 256 + (uint32_t)kk * 32 + a_colh));
#pragma unroll
        for (int q = 0; q < 4; ++q) {
            uint32_t b[4];
            ldsm_x4_t(b, sb + SM_B + swz((kk * 16 + b_krow) * 256 +
                                         (uint32_t)(nh * 4 + q) * 32 + b_half));
            mma_bf16(acc[2 * q],     a, b[0], b[1]);
            mma_bf16(acc[2 * q + 1], a, b[2], b[3]);
        }
    }

    // Epilogue. D layout m16n8: c0,c1 -> row (lane>>2); c2,c3 -> row +8.
    const int rl_lo = rg * 16 + (lane >> 2);   // local row 0..63
    const int m_lo  = r0 + rl_lo;
    const int m_hi  = m_lo + 8;
    uint32_t* items32 = reinterpret_cast<uint32_t*>(g_itemh);
    float d1lo = 0.f, d2lo = 0.f, d1hi = 0.f, d2hi = 0.f;

#pragma unroll
    for (int nf = 0; nf < 8; ++nf) {
        const int col = nh * 64 + nf * 8 + (lane & 3) * 2;
        const float bx = s_bias[col], by = s_bias[col + 1];
        const float w1x = s_watt[col], w1y = s_watt[col + 1];
        const float w2x = s_watt[128 + col], w2y = s_watt[128 + col + 1];

        const float o0 = acc[nf][0] + bx, o1 = acc[nf][1] + by;
        const float p0 = acc[nf][2] + bx, p1 = acc[nf][3] + by;
        d1lo += o0 * w1x + o1 * w1y;  d2lo += o0 * w2x + o1 * w2y;
        d1hi += p0 * w1x + p1 * w1y;  d2hi += p0 * w2x + p1 * w2y;

        const __nv_bfloat162 hlo = __float22bfloat162_rn(make_float2(o0, o1));
        const __nv_bfloat162 hhi = __float22bfloat162_rn(make_float2(p0, p1));
        if (m_lo < M_ITEMS) items32[(uint32_t)m_lo * 64u + (uint32_t)(col >> 1)] = *reinterpret_cast<const uint32_t*>(&hlo);
        if (m_hi < M_ITEMS) items32[(uint32_t)m_hi * 64u + (uint32_t)(col >> 1)] = *reinterpret_cast<const uint32_t*>(&hhi);
    }

    // quad-reduce within the warp (fixed order), stage halves to smem
#pragma unroll
    for (int off = 1; off <= 2; off <<= 1) {
        d1lo += __shfl_xor_sync(0xFFFFFFFFu, d1lo, off);
        d2lo += __shfl_xor_sync(0xFFFFFFFFu, d2lo, off);
        d1hi += __shfl_xor_sync(0xFFFFFFFFu, d1hi, off);
        d2hi += __shfl_xor_sync(0xFFFFFFFFu, d2hi, off);
    }
    if ((lane & 3) == 0) {
        s_red[rl_lo * 4 + nh * 2 + 0] = d1lo;
        s_red[rl_lo * 4 + nh * 2 + 1] = d2lo;
        s_red[(rl_lo + 8) * 4 + nh * 2 + 0] = d1hi;
        s_red[(rl_lo + 8) * 4 + nh * 2 + 1] = d2hi;
    }
    __syncthreads();
    if (tid < 64) {
        const int m = r0 + tid;
        if (m < M_ITEMS) {
            g_a1[m] = s_red[tid * 4 + 0] + s_red[tid * 4 + 2];
            g_a2[m] = s_red[tid * 4 + 1] + s_red[tid * 4 + 3];
        }
    }
}

// ---------------------------------------------------------------------------
// K2: fused edge pass with per-block dtype sniff (int64 high-halves are 0).
// Precomputes all 640k scores with full MLP (independent edges).
// ---------------------------------------------------------------------------
__global__ void __launch_bounds__(256) k_edge(const int* __restrict__ ew,
                                              const float* __restrict__ batt) {
    __shared__ unsigned int s_or[8];
    const int e    = blockIdx.x * 256 + threadIdx.x;   // NE % 256 == 0
    const int lane = threadIdx.x & 31;

    const unsigned int odd = ((const unsigned int*)ew)[2 * e + 1];
    unsigned int v = odd;
#pragma unroll
    for (int o = 16; o; o >>= 1) v |= __shfl_xor_sync(0xFFFFFFFFu, v, o);
    if (lane == 0) s_or[threadIdx.x >> 5] = v;
    __syncthreads();
    const unsigned int t = s_or[0] | s_or[1] | s_or[2] | s_or[3] |
                           s_or[4] | s_or[5] | s_or[6] | s_or[7];
    const bool is64 = (t == 0u);

    int src, dst;
    if (is64) { src = ew[4 * e]; dst = ew[4 * e + 2]; }
    else      { src = ew[2 * e]; dst = (int)odd; }

    float att = g_a1[src] + g_a2[dst] + batt[0];
    att = att > 0.f ? att : 0.2f * att;                    // leaky_relu(0.2)
    const float sc = __expf(att - 1.0f);
    g_ds[e] = make_int2(dst, __float_as_int(sc));

    // segment boundaries (race-free: disjoint ranges per thread)
    const int sprev = (e == 0) ? -1 : (is64 ? ew[4 * e - 4] : ew[2 * e - 2]);
    if (src != sprev) {
        for (int q = sprev + 1; q <= src; ++q) g_segstart[q] = e;
    }
    if (e == NE - 1) {
        for (int q = src + 1; q <= M_ITEMS; ++q) g_segstart[q] = NE;
    }
}

// ---------------------------------------------------------------------------
// K3: warp-per-segment gather-aggregate, 16-lanes-per-edge LDG.128. (R14 form)
// ---------------------------------------------------------------------------
__global__ void __launch_bounds__(128) k_agg(float* __restrict__ out) {
    const int seg  = blockIdx.x * 4 + (threadIdx.x >> 5);
    const int lane = threadIdx.x & 31;
    if (seg >= M_ITEMS) return;

    const int lo = __ldg(&g_segstart[seg]);
    const int hi = __ldg(&g_segstart[seg + 1]);
    const int eh = lane >> 4;        // which edge of the pair (0/1)
    const int lq = lane & 15;        // 16B chunk within the 256B row

    const uint4* itemv = reinterpret_cast<const uint4*>(g_itemh);   // row = 16 uint4
    ull acc2[4] = {0ull, 0ull, 0ull, 0ull};
    float ssum = 0.f;

    for (int base = lo; base < hi; base += 32) {
        const int cnt = min(32, hi - base);
        int   dst = 0;
        float sc  = 0.f;
        if (lane < cnt) {
            const int2 ds = g_ds[base + lane];
            dst = ds.x;
            sc  = __int_as_float(ds.y);
        }
        ssum += sc;   // per-lane partial, fixed order

        for (int j = 0; j < cnt; j += 16) {   // 16 edges per batch, zero-padded
            int d[8]; float c[8]; uint4 v[8];
#pragma unroll
            for (int u = 0; u < 8; ++u) {
                d[u] = __shfl_sync(0xFFFFFFFFu, dst, j + 2 * u + eh);  // padded -> 0
                c[u] = __shfl_sync(0xFFFFFFFFu, sc,  j + 2 * u + eh);  // padded -> 0.0
            }
#pragma unroll
            for (int u = 0; u < 8; ++u) v[u] = itemv[d[u] * 16 + lq]; // 32-bit offset
#pragma unroll
            for (int u = 0; u < 8; ++u) {
                const ull cc = pk2(c[u], c[u]);
                const uint32_t* pv = reinterpret_cast<const uint32_t*>(&v[u]);
#pragma unroll
                for (int q = 0; q < 4; ++q) {
                    const float flo = __uint_as_float(pv[q] << 16);          // exact
                    const float fhi = __uint_as_float(pv[q] & 0xffff0000u);  // exact
                    fma2(acc2[q], pk2(flo, fhi), cc);
                }
            }
        }
    }

    // unpack, combine pair halves (fixed order) + score total reduce
    float acc[8];
#pragma unroll
    for (int q = 0; q < 4; ++q) upk2(acc2[q], acc[2 * q], acc[2 * q + 1]);
#pragma unroll
    for (int q = 0; q < 8; ++q) acc[q] += __shfl_xor_sync(0xFFFFFFFFu, acc[q], 16);
#pragma unroll
    for (int o = 16; o; o >>= 1) ssum += __shfl_xor_sync(0xFFFFFFFFu, ssum, o);
    const float inv = (hi > lo) ? 1.f / ssum : 0.f;

    float4 r;
    r.x = 1.f / (1.f + __expf(-acc[eh * 4 + 0] * inv));
    r.y = 1.f / (1.f + __expf(-acc[eh * 4 + 1] * inv));
    r.z = 1.f / (1.f + __expf(-acc[eh * 4 + 2] * inv));
    r.w = 1.f / (1.f + __expf(-acc[eh * 4 + 3] * inv));
    reinterpret_cast<float4*>(out)[(size_t)seg * 32 + lq * 2 + eh] = r;
}

// ---------------------------------------------------------------------------
extern "C" void kernel_launch(void* const* d_in, const int* in_sizes, int n_in,
                              void* d_out, int out_size) {
    const float* emb  = (const float*)d_in[0];      // (20001, 128) f32
    const int*   edge = (const int*)d_in[1];        // (640000, 2) int (32/64-bit, sniffed)
    const float* W    = (const float*)d_in[2];      // (128, 128) f32
    const float* b    = (const float*)d_in[3];      // (128,) f32
    const float* Watt = (const float*)d_in[4];      // (256, 1) f32
    const float* batt = (const float*)d_in[5];      // (1,) f32
    float*       out  = (float*)d_out;              // (20001, 128) f32

    cudaFuncSetAttribute(k_gemm, cudaFuncAttributeMaxDynamicSharedMemorySize, SM_TOTAL);

    k_prep<<<8, 128>>>(W);
    k_gemm<<<(M_ITEMS + TILE_M - 1) / TILE_M, 256, SM_TOTAL>>>(emb, b, Watt);   // 313 CTAs
    k_edge<<<NE / 256, 256>>>(edge, batt);
    k_agg <<<(M_ITEMS + 3) / 4, 128>>>(out);
}

// round 16
// speedup vs baseline: 1.0831x; 1.0831x over previous
#include <cuda_runtime.h>
#include <cuda_bf16.h>
#include <cstdint>

// Problem constants (fixed by the reference)
#define M_ITEMS 20001      // emb rows / segments
#define EDIM    128
#define NE      640000     // edges (divisible by 256)
#define TILE_M  64         // rows per CTA in the MMA GEMM

typedef unsigned long long ull;

// Scratch (device globals: no runtime allocation allowed)
__device__ __nv_bfloat16 g_itemh[M_ITEMS * EDIM]; // item_scaled in bf16 (gather table)
__device__ float g_a1[M_ITEMS];            // item_scaled . W_att[:128]
__device__ float g_a2[M_ITEMS];            // item_scaled . W_att[128:]
__device__ int2  g_ds[NE];                 // packed (dst, score_bits) per edge
__device__ int   g_segstart[M_ITEMS + 1];  // segment boundaries (edges sorted by src)

// ---------------- warp-MMA helpers (sm_80-class PTX: valid on sm_103) ------
__device__ __forceinline__ uint32_t smem_u32(const void* p) {
    uint32_t a;
    asm("{ .reg .u64 t; cvta.to.shared.u64 t, %1; cvt.u32.u64 %0, t; }" : "=r"(a) : "l"(p));
    return a;
}
// swizzle: XOR row bits (8..10) into the 16B-chunk selector (bits 4..6).
__device__ __forceinline__ uint32_t swz(uint32_t off) {
    return off ^ (((off >> 8) & 7u) << 4);
}
__device__ __forceinline__ void ldsm_x4(uint32_t* r, uint32_t addr) {
    asm volatile("ldmatrix.sync.aligned.m8n8.x4.shared.b16 {%0,%1,%2,%3}, [%4];"
                 : "=r"(r[0]), "=r"(r[1]), "=r"(r[2]), "=r"(r[3]) : "r"(addr));
}
__device__ __forceinline__ void ldsm_x4_t(uint32_t* r, uint32_t addr) {
    asm volatile("ldmatrix.sync.aligned.m8n8.x4.trans.shared.b16 {%0,%1,%2,%3}, [%4];"
                 : "=r"(r[0]), "=r"(r[1]), "=r"(r[2]), "=r"(r[3]) : "r"(addr));
}
__device__ __forceinline__ void mma_bf16(float* c, const uint32_t* a, uint32_t b0, uint32_t b1) {
    asm volatile("mma.sync.aligned.m16n8k16.row.col.f32.bf16.bf16.f32 "
                 "{%0,%1,%2,%3}, {%4,%5,%6,%7}, {%8,%9}, {%0,%1,%2,%3};"
                 : "+f"(c[0]), "+f"(c[1]), "+f"(c[2]), "+f"(c[3])
                 : "r"(a[0]), "r"(a[1]), "r"(a[2]), "r"(a[3]), "r"(b0), "r"(b1));
}
// packed fp32x2 FMA (Blackwell FFMA2; exact per-lane fp32 semantics)
__device__ __forceinline__ void fma2(ull& d, ull a, ull b) {
    asm("fma.rn.f32x2 %0, %1, %2, %0;" : "+l"(d) : "l"(a), "l"(b));
}
__device__ __forceinline__ ull pk2(float lo, float hi) {
    ull r; asm("mov.b64 %0, {%1, %2};" : "=l"(r) : "f"(lo), "f"(hi)); return r;
}
__device__ __forceinline__ void upk2(ull v, float& lo, float& hi) {
    asm("mov.b64 {%0, %1}, %2;" : "=f"(lo), "=f"(hi) : "l"(v));
}

// Dynamic smem layout: [0,512) bias, [512,1536) Watt, [2048,18432) sA bf16
// [64 rows x 256B], [18432,51200) sB bf16 [128 k-rows x 256B].
#define SM_BIAS  0
#define SM_WATT  512
#define SM_A     2048
#define SM_B     (2048 + 16384)
#define SM_TOTAL (2048 + 16384 + 32768)

// ---------------------------------------------------------------------------
// K1: item_scaled = emb @ W + b via warp-level bf16 HMMA (fp32 accumulate).
// CTA = 64 rows, 128 threads (4 warps x 16 rows, full N per warp).  (R11 form)
// ---------------------------------------------------------------------------
__global__ void __launch_bounds__(128) k_gemm(const float* __restrict__ A,
                                              const float* __restrict__ W,
                                              const float* __restrict__ bias,
                                              const float* __restrict__ Watt) {
    extern __shared__ unsigned char smem_raw[];
    const uint32_t sb = smem_u32(smem_raw);
    float* s_bias = reinterpret_cast<float*>(smem_raw + SM_BIAS);
    float* s_watt = reinterpret_cast<float*>(smem_raw + SM_WATT);

    const int tid  = threadIdx.x;
    const int w    = tid >> 5;
    const int lane = tid & 31;
    const int r0   = blockIdx.x * TILE_M;

    s_bias[tid] = bias[tid];
    s_watt[tid] = Watt[tid];
    s_watt[tid + 128] = Watt[tid + 128];

    // fill sA (A rows r0..r0+63 -> bf16): 2048 float4 groups
#pragma unroll
    for (int i = 0; i < 16; ++i) {
        const int idx = tid + i * 128;
        const int row = idx >> 5;
        const int cg  = idx & 31;
        const int gr  = min(r0 + row, M_ITEMS - 1);
        const float4 v = reinterpret_cast<const float4*>(A)[(size_t)gr * 32 + cg];
        const __nv_bfloat162 h0 = __float22bfloat162_rn(make_float2(v.x, v.y));
        const __nv_bfloat162 h1 = __float22bfloat162_rn(make_float2(v.z, v.w));
        uint2 pk;
        pk.x = *reinterpret_cast<const uint32_t*>(&h0);
        pk.y = *reinterpret_cast<const uint32_t*>(&h1);
        *reinterpret_cast<uint2*>(smem_raw + SM_A + swz(row * 256 + cg * 8)) = pk;
    }
    // fill sB (W row-major [K=128][N=128] -> bf16): 4096 float4 groups
#pragma unroll
    for (int i = 0; i < 32; ++i) {
        const int idx = tid + i * 128;
        const int row = idx >> 5;
        const int cg  = idx & 31;
        const float4 v = reinterpret_cast<const float4*>(W)[(size_t)row * 32 + cg];
        const __nv_bfloat162 h0 = __float22bfloat162_rn(make_float2(v.x, v.y));
        const __nv_bfloat162 h1 = __float22bfloat162_rn(make_float2(v.z, v.w));
        uint2 pk;
        pk.x = *reinterpret_cast<const uint32_t*>(&h0);
        pk.y = *reinterpret_cast<const uint32_t*>(&h1);
        *reinterpret_cast<uint2*>(smem_raw + SM_B + swz(row * 256 + cg * 8)) = pk;
    }
    __syncthreads();

    float acc[16][4];
#pragma unroll
    for (int nf = 0; nf < 16; ++nf)
#pragma unroll
        for (int c = 0; c < 4; ++c) acc[nf][c] = 0.f;

    const uint32_t a_row  = (uint32_t)(w * 16 + (lane & 7) + ((lane >> 3) & 1) * 8);
    const uint32_t a_colh = (uint32_t)((lane >> 4) & 1) * 16;
    const uint32_t b_krow = (uint32_t)(lane & 15);
    const uint32_t b_half = (uint32_t)((lane >> 4) & 1) * 16;

#pragma unroll
    for (int kk = 0; kk < 8; ++kk) {
        uint32_t a[4];
        ldsm_x4(a, sb + SM_A + swz(a_row * 256 + (uint32_t)kk * 32 + a_colh));
#pragma unroll
        for (int p = 0; p < 8; ++p) {
            uint32_t b[4];
            ldsm_x4_t(b, sb + SM_B + swz((kk * 16 + b_krow) * 256 + (uint32_t)p * 32 + b_half));
            mma_bf16(acc[2 * p],     a, b[0], b[1]);
            mma_bf16(acc[2 * p + 1], a, b[2], b[3]);
        }
    }

    // Epilogue. D layout m16n8: c0,c1 -> row (lane>>2); c2,c3 -> row +8.
    const int m_lo = r0 + w * 16 + (lane >> 2);
    const int m_hi = m_lo + 8;
    uint32_t* items32 = reinterpret_cast<uint32_t*>(g_itemh);
    float d1lo = 0.f, d2lo = 0.f, d1hi = 0.f, d2hi = 0.f;

#pragma unroll
    for (int nf = 0; nf < 16; ++nf) {
        const int col = nf * 8 + (lane & 3) * 2;
        const float bx = s_bias[col], by = s_bias[col + 1];
        const float w1x = s_watt[col], w1y = s_watt[col + 1];
        const float w2x = s_watt[128 + col], w2y = s_watt[128 + col + 1];

        const float o0 = acc[nf][0] + bx, o1 = acc[nf][1] + by;
        const float p0 = acc[nf][2] + bx, p1 = acc[nf][3] + by;
        d1lo += o0 * w1x + o1 * w1y;  d2lo += o0 * w2x + o1 * w2y;
        d1hi += p0 * w1x + p1 * w1y;  d2hi += p0 * w2x + p1 * w2y;

        const __nv_bfloat162 hlo = __float22bfloat162_rn(make_float2(o0, o1));
        const __nv_bfloat162 hhi = __float22bfloat162_rn(make_float2(p0, p1));
        if (m_lo < M_ITEMS) items32[(uint32_t)m_lo * 64u + (uint32_t)(col >> 1)] = *reinterpret_cast<const uint32_t*>(&hlo);
        if (m_hi < M_ITEMS) items32[(uint32_t)m_hi * 64u + (uint32_t)(col >> 1)] = *reinterpret_cast<const uint32_t*>(&hhi);
    }

#pragma unroll
    for (int off = 1; off <= 2; off <<= 1) {
        d1lo += __shfl_xor_sync(0xFFFFFFFFu, d1lo, off);
        d2lo += __shfl_xor_sync(0xFFFFFFFFu, d2lo, off);
        d1hi += __shfl_xor_sync(0xFFFFFFFFu, d1hi, off);
        d2hi += __shfl_xor_sync(0xFFFFFFFFu, d2hi, off);
    }
    if ((lane & 3) == 0) {
        if (m_lo < M_ITEMS) { g_a1[m_lo] = d1lo; g_a2[m_lo] = d2lo; }
        if (m_hi < M_ITEMS) { g_a1[m_hi] = d1hi; g_a2[m_hi] = d2hi; }
    }
}

// ---------------------------------------------------------------------------
// K2: fused edge pass with per-block dtype sniff (int64 high-halves are 0).
// Precomputes all 640k scores with full MLP (independent edges).
// ---------------------------------------------------------------------------
__global__ void __launch_bounds__(256) k_edge(const int* __restrict__ ew,
                                              const float* __restrict__ batt) {
    __shared__ unsigned int s_or[8];
    const int e    = blockIdx.x * 256 + threadIdx.x;   // NE % 256 == 0
    const int lane = threadIdx.x & 31;

    const unsigned int odd = ((const unsigned int*)ew)[2 * e + 1];
    unsigned int v = odd;
#pragma unroll
    for (int o = 16; o; o >>= 1) v |= __shfl_xor_sync(0xFFFFFFFFu, v, o);
    if (lane == 0) s_or[threadIdx.x >> 5] = v;
    __syncthreads();
    const unsigned int t = s_or[0] | s_or[1] | s_or[2] | s_or[3] |
                           s_or[4] | s_or[5] | s_or[6] | s_or[7];
    const bool is64 = (t == 0u);

    int src, dst;
    if (is64) { src = ew[4 * e]; dst = ew[4 * e + 2]; }
    else      { src = ew[2 * e]; dst = (int)odd; }

    float att = g_a1[src] + g_a2[dst] + batt[0];
    att = att > 0.f ? att : 0.2f * att;                    // leaky_relu(0.2)
    const float sc = __expf(att - 1.0f);
    g_ds[e] = make_int2(dst, __float_as_int(sc));

    // segment boundaries (race-free: disjoint ranges per thread)
    const int sprev = (e == 0) ? -1 : (is64 ? ew[4 * e - 4] : ew[2 * e - 2]);
    if (src != sprev) {
        for (int q = sprev + 1; q <= src; ++q) g_segstart[q] = e;
    }
    if (e == NE - 1) {
        for (int q = src + 1; q <= M_ITEMS; ++q) g_segstart[q] = NE;
    }
}

// ---------------------------------------------------------------------------
// K3: warp-per-segment gather-aggregate, 16-lanes-per-edge LDG.128.
// Occupancy-first tuning: 4-pair (8-edge) prefetch batches cut the register
// footprint (~51 -> ~40 regs) so 12 CTAs/SM fit (launch_bounds(128,12)):
// in-flight loads per SM stay ~constant while 50% more warps interleave the
// serial shuffle/FFMA2 work. Per-lane accumulation order identical to R14
// -> bit-identical output. Zero-padded batches; fixed reduction orders.
// ---------------------------------------------------------------------------
__global__ void __launch_bounds__(128, 12) k_agg(float* __restrict__ out) {
    const int seg  = blockIdx.x * 4 + (threadIdx.x >> 5);
    const int lane = threadIdx.x & 31;
    if (seg >= M_ITEMS) return;

    const int lo = __ldg(&g_segstart[seg]);
    const int hi = __ldg(&g_segstart[seg + 1]);
    const int eh = lane >> 4;        // which edge of the pair (0/1)
    const int lq = lane & 15;        // 16B chunk within the 256B row

    const uint4* itemv = reinterpret_cast<const uint4*>(g_itemh);   // row = 16 uint4
    ull acc2[4] = {0ull, 0ull, 0ull, 0ull};
    float ssum = 0.f;

    for (int base = lo; base < hi; base += 32) {
        const int cnt = min(32, hi - base);
        int   dst = 0;
        float sc  = 0.f;
        if (lane < cnt) {
            const int2 ds = g_ds[base + lane];
            dst = ds.x;
            sc  = __int_as_float(ds.y);
        }
        ssum += sc;   // per-lane partial, fixed order

        for (int j = 0; j < cnt; j += 8) {    // 8 edges (4 pairs) per batch, zero-padded
            int d[4]; float c[4]; uint4 v[4];
#pragma unroll
            for (int u = 0; u < 4; ++u) {
                d[u] = __shfl_sync(0xFFFFFFFFu, dst, j + 2 * u + eh);  // padded -> 0
                c[u] = __shfl_sync(0xFFFFFFFFu, sc,  j + 2 * u + eh);  // padded -> 0.0
            }
#pragma unroll
            for (int u = 0; u < 4; ++u) v[u] = itemv[d[u] * 16 + lq]; // 32-bit offset
#pragma unroll
            for (int u = 0; u < 4; ++u) {
                const ull cc = pk2(c[u], c[u]);
                const uint32_t* pv = reinterpret_cast<const uint32_t*>(&v[u]);
#pragma unroll
                for (int q = 0; q < 4; ++q) {
                    const float flo = __uint_as_float(pv[q] << 16);          // exact
                    const float fhi = __uint_as_float(pv[q] & 0xffff0000u);  // exact
                    fma2(acc2[q], pk2(flo, fhi), cc);
                }
            }
        }
    }

    // unpack, combine pair halves (fixed order) + score total reduce
    float acc[8];
#pragma unroll
    for (int q = 0; q < 4; ++q) upk2(acc2[q], acc[2 * q], acc[2 * q + 1]);
#pragma unroll
    for (int q = 0; q < 8; ++q) acc[q] += __shfl_xor_sync(0xFFFFFFFFu, acc[q], 16);
#pragma unroll
    for (int o = 16; o; o >>= 1) ssum += __shfl_xor_sync(0xFFFFFFFFu, ssum, o);
    const float inv = (hi > lo) ? 1.f / ssum : 0.f;

    float4 r;
    r.x = 1.f / (1.f + __expf(-acc[eh * 4 + 0] * inv));
    r.y = 1.f / (1.f + __expf(-acc[eh * 4 + 1] * inv));
    r.z = 1.f / (1.f + __expf(-acc[eh * 4 + 2] * inv));
    r.w = 1.f / (1.f + __expf(-acc[eh * 4 + 3] * inv));
    reinterpret_cast<float4*>(out)[(size_t)seg * 32 + lq * 2 + eh] = r;
}

// ---------------------------------------------------------------------------
extern "C" void kernel_launch(void* const* d_in, const int* in_sizes, int n_in,
                              void* d_out, int out_size) {
    const float* emb  = (const float*)d_in[0];      // (20001, 128) f32
    const int*   edge = (const int*)d_in[1];        // (640000, 2) int (32/64-bit, sniffed)
    const float* W    = (const float*)d_in[2];      // (128, 128) f32
    const float* b    = (const float*)d_in[3];      // (128,) f32
    const float* Watt = (const float*)d_in[4];      // (256, 1) f32
    const float* batt = (const float*)d_in[5];      // (1,) f32
    float*       out  = (float*)d_out;              // (20001, 128) f32

    cudaFuncSetAttribute(k_gemm, cudaFuncAttributeMaxDynamicSharedMemorySize, SM_TOTAL);

    k_gemm<<<(M_ITEMS + TILE_M - 1) / TILE_M, 128, SM_TOTAL>>>(emb, W, b, Watt); // 313 CTAs
    k_edge<<<NE / 256, 256>>>(edge, batt);
    k_agg <<<(M_ITEMS + 3) / 4, 128>>>(out);
}

// round 17
// speedup vs baseline: 1.1029x; 1.0183x over previous
#include <cuda_runtime.h>
#include <cuda_bf16.h>
#include <cstdint>

// Problem constants (fixed by the reference)
#define M_ITEMS 20001      // emb rows / segments
#define EDIM    128
#define NE      640000     // edges (divisible by 256)
#define TILE_M  32         // rows per CTA in the MMA GEMM

typedef unsigned long long ull;

// Scratch (device globals: no runtime allocation allowed)
__device__ __nv_bfloat16 g_itemh[M_ITEMS * EDIM]; // item_scaled in bf16 (gather table)
__device__ float g_a1[M_ITEMS];            // item_scaled . W_att[:128]
__device__ float g_a2[M_ITEMS];            // item_scaled . W_att[128:]
__device__ int2  g_ds[NE];                 // packed (dst, score_bits) per edge
__device__ int   g_segstart[M_ITEMS + 1];  // segment boundaries (edges sorted by src)
__device__ alignas(16) unsigned char g_wbf[32768]; // W as pre-swizzled bf16 smem image

// ---------------- warp-MMA helpers (sm_80-class PTX: valid on sm_103) ------
__device__ __forceinline__ uint32_t smem_u32(const void* p) {
    uint32_t a;
    asm("{ .reg .u64 t; cvta.to.shared.u64 t, %1; cvt.u32.u64 %0, t; }" : "=r"(a) : "l"(p));
    return a;
}
// swizzle: XOR row bits (8..10) into the 16B-chunk selector (bits 4..6).
__device__ __forceinline__ uint32_t swz(uint32_t off) {
    return off ^ (((off >> 8) & 7u) << 4);
}
__device__ __forceinline__ void ldsm_x4(uint32_t* r, uint32_t addr) {
    asm volatile("ldmatrix.sync.aligned.m8n8.x4.shared.b16 {%0,%1,%2,%3}, [%4];"
                 : "=r"(r[0]), "=r"(r[1]), "=r"(r[2]), "=r"(r[3]) : "r"(addr));
}
__device__ __forceinline__ void ldsm_x4_t(uint32_t* r, uint32_t addr) {
    asm volatile("ldmatrix.sync.aligned.m8n8.x4.trans.shared.b16 {%0,%1,%2,%3}, [%4];"
                 : "=r"(r[0]), "=r"(r[1]), "=r"(r[2]), "=r"(r[3]) : "r"(addr));
}
__device__ __forceinline__ void mma_bf16(float* c, const uint32_t* a, uint32_t b0, uint32_t b1) {
    asm volatile("mma.sync.aligned.m16n8k16.row.col.f32.bf16.bf16.f32 "
                 "{%0,%1,%2,%3}, {%4,%5,%6,%7}, {%8,%9}, {%0,%1,%2,%3};"
                 : "+f"(c[0]), "+f"(c[1]), "+f"(c[2]), "+f"(c[3])
                 : "r"(a[0]), "r"(a[1]), "r"(a[2]), "r"(a[3]), "r"(b0), "r"(b1));
}
// packed fp32x2 FMA (Blackwell FFMA2; exact per-lane fp32 semantics)
__device__ __forceinline__ void fma2(ull& d, ull a, ull b) {
    asm("fma.rn.f32x2 %0, %1, %2, %0;" : "+l"(d) : "l"(a), "l"(b));
}
__device__ __forceinline__ ull pk2(float lo, float hi) {
    ull r; asm("mov.b64 %0, {%1, %2};" : "=l"(r) : "f"(lo), "f"(hi)); return r;
}
__device__ __forceinline__ void upk2(ull v, float& lo, float& hi) {
    asm("mov.b64 {%0, %1}, %2;" : "=f"(lo), "=f"(hi) : "l"(v));
}
__device__ __forceinline__ void cp_async16(uint32_t smem_dst, const void* gsrc) {
    asm volatile("cp.async.cg.shared.global [%0], [%1], 16;" :: "r"(smem_dst), "l"(gsrc));
}

// Dynamic smem layout: [0,512) bias, [512,1536) Watt, [1536,2048) a1/a2
// reduce buffer (32 rows x 4 floats), [2048,10240) sA bf16 [32 rows x 256B],
// [10240,43008) sB bf16 [128 k-rows x 256B].
#define SM_BIAS  0
#define SM_WATT  512
#define SM_RED   1536
#define SM_A     2048
#define SM_B     10240
#define SM_TOTAL (10240 + 32768)

// ---------------------------------------------------------------------------
// K0: one-time W -> pre-swizzled bf16 image (exact smem B layout).
// ---------------------------------------------------------------------------
__global__ void __launch_bounds__(128) k_prep(const float* __restrict__ W) {
    const int idx = blockIdx.x * 128 + threadIdx.x;   // 0..1023
#pragma unroll
    for (int i = 0; i < 4; ++i) {
        const int g   = idx + i * 1024;               // 0..4095 float4 groups
        const int row = g >> 5;                       // k row 0..127
        const int cg  = g & 31;
        const float4 v = reinterpret_cast<const float4*>(W)[(size_t)row * 32 + cg];
        const __nv_bfloat162 h0 = __float22bfloat162_rn(make_float2(v.x, v.y));
        const __nv_bfloat162 h1 = __float22bfloat162_rn(make_float2(v.z, v.w));
        uint2 pk;
        pk.x = *reinterpret_cast<const uint32_t*>(&h0);
        pk.y = *reinterpret_cast<const uint32_t*>(&h1);
        *reinterpret_cast<uint2*>(g_wbf + swz(row * 256 + cg * 8)) = pk;
    }
}

// ---------------------------------------------------------------------------
// K1: item_scaled = emb @ W + b via warp-level bf16 HMMA (fp32 accumulate).
// CTA = 32 rows, 128 threads (4 warps): warp w = (row-group w>>1, N-half w&1),
// 16 rows x 64 cols each. 626 CTAs (~4.2/SM, ~17 warps/SM). B tile arrives
// via raw cp.async of the pre-swizzled image (no CVT), streaming behind the
// A convert. a1/a2: per-warp quad-reduce -> smem -> fixed-order combine.
// ---------------------------------------------------------------------------
__global__ void __launch_bounds__(128) k_gemm(const float* __restrict__ A,
                                              const float* __restrict__ bias,
                                              const float* __restrict__ Watt) {
    extern __shared__ unsigned char smem_raw[];
    const uint32_t sb = smem_u32(smem_raw);
    float* s_bias = reinterpret_cast<float*>(smem_raw + SM_BIAS);
    float* s_watt = reinterpret_cast<float*>(smem_raw + SM_WATT);
    float* s_red  = reinterpret_cast<float*>(smem_raw + SM_RED);   // [32][4]

    const int tid  = threadIdx.x;
    const int w    = tid >> 5;
    const int lane = tid & 31;
    const int rg   = w >> 1;        // row group 0/1 (16 rows)
    const int nh   = w & 1;         // N half 0/1 (64 cols)
    const int r0   = blockIdx.x * TILE_M;

    // B tile: 2048 x 16B raw async copies (pre-swizzled bf16), issued first.
#pragma unroll
    for (int i = 0; i < 16; ++i) {
        const uint32_t off = (uint32_t)(tid + i * 128) * 16;
        cp_async16(sb + SM_B + off, g_wbf + off);
    }
    asm volatile("cp.async.commit_group;" ::: "memory");

    s_bias[tid] = bias[tid];
    s_watt[tid] = Watt[tid];
    s_watt[tid + 128] = Watt[tid + 128];

    // fill sA (A rows r0..r0+31 -> bf16): 1024 float4 groups over 128 threads
#pragma unroll
    for (int i = 0; i < 8; ++i) {
        const int idx = tid + i * 128;
        const int row = idx >> 5;             // 0..31
        const int cg  = idx & 31;
        const int gr  = min(r0 + row, M_ITEMS - 1);
        const float4 v = reinterpret_cast<const float4*>(A)[(size_t)gr * 32 + cg];
        const __nv_bfloat162 h0 = __float22bfloat162_rn(make_float2(v.x, v.y));
        const __nv_bfloat162 h1 = __float22bfloat162_rn(make_float2(v.z, v.w));
        uint2 pk;
        pk.x = *reinterpret_cast<const uint32_t*>(&h0);
        pk.y = *reinterpret_cast<const uint32_t*>(&h1);
        *reinterpret_cast<uint2*>(smem_raw + SM_A + swz(row * 256 + cg * 8)) = pk;
    }
    asm volatile("cp.async.wait_group 0;" ::: "memory");
    __syncthreads();

    // accumulators: 8 n-frags x 4 fp32 (this warp's 64-col half)
    float acc[8][4];
#pragma unroll
    for (int nf = 0; nf < 8; ++nf)
#pragma unroll
        for (int c = 0; c < 4; ++c) acc[nf][c] = 0.f;

    const uint32_t a_row  = (uint32_t)(rg * 16 + (lane & 7) + ((lane >> 3) & 1) * 8);
    const uint32_t a_colh = (uint32_t)((lane >> 4) & 1) * 16;
    const uint32_t b_krow = (uint32_t)(lane & 15);
    const uint32_t b_half = (uint32_t)((lane >> 4) & 1) * 16;

#pragma unroll
    for (int kk = 0; kk < 8; ++kk) {
        uint32_t a[4];
        ldsm_x4(a, sb + SM_A + swz(a_row * 256 + (uint32_t)kk * 32 + a_colh));
#pragma unroll
        for (int q = 0; q < 4; ++q) {
            uint32_t b[4];
            ldsm_x4_t(b, sb + SM_B + swz((kk * 16 + b_krow) * 256 +
                                         (uint32_t)(nh * 4 + q) * 32 + b_half));
            mma_bf16(acc[2 * q],     a, b[0], b[1]);
            mma_bf16(acc[2 * q + 1], a, b[2], b[3]);
        }
    }

    // Epilogue. D layout m16n8: c0,c1 -> row (lane>>2); c2,c3 -> row +8.
    const int rl_lo = rg * 16 + (lane >> 2);   // local row 0..31
    const int m_lo  = r0 + rl_lo;
    const int m_hi  = m_lo + 8;
    uint32_t* items32 = reinterpret_cast<uint32_t*>(g_itemh);
    float d1lo = 0.f, d2lo = 0.f, d1hi = 0.f, d2hi = 0.f;

#pragma unroll
    for (int nf = 0; nf < 8; ++nf) {
        const int col = nh * 64 + nf * 8 + (lane & 3) * 2;
        const float bx = s_bias[col], by = s_bias[col + 1];
        const float w1x = s_watt[col], w1y = s_watt[col + 1];
        const float w2x = s_watt[128 + col], w2y = s_watt[128 + col + 1];

        const float o0 = acc[nf][0] + bx, o1 = acc[nf][1] + by;
        const float p0 = acc[nf][2] + bx, p1 = acc[nf][3] + by;
        d1lo += o0 * w1x + o1 * w1y;  d2lo += o0 * w2x + o1 * w2y;
        d1hi += p0 * w1x + p1 * w1y;  d2hi += p0 * w2x + p1 * w2y;

        const __nv_bfloat162 hlo = __float22bfloat162_rn(make_float2(o0, o1));
        const __nv_bfloat162 hhi = __float22bfloat162_rn(make_float2(p0, p1));
        if (m_lo < M_ITEMS) items32[(uint32_t)m_lo * 64u + (uint32_t)(col >> 1)] = *reinterpret_cast<const uint32_t*>(&hlo);
        if (m_hi < M_ITEMS) items32[(uint32_t)m_hi * 64u + (uint32_t)(col >> 1)] = *reinterpret_cast<const uint32_t*>(&hhi);
    }

    // quad-reduce within the warp (fixed order), stage halves to smem
#pragma unroll
    for (int off = 1; off <= 2; off <<= 1) {
        d1lo += __shfl_xor_sync(0xFFFFFFFFu, d1lo, off);
        d2lo += __shfl_xor_sync(0xFFFFFFFFu, d2lo, off);
        d1hi += __shfl_xor_sync(0xFFFFFFFFu, d1hi, off);
        d2hi += __shfl_xor_sync(0xFFFFFFFFu, d2hi, off);
    }
    if ((lane & 3) == 0) {
        s_red[rl_lo * 4 + nh * 2 + 0] = d1lo;
        s_red[rl_lo * 4 + nh * 2 + 1] = d2lo;
        s_red[(rl_lo + 8) * 4 + nh * 2 + 0] = d1hi;
        s_red[(rl_lo + 8) * 4 + nh * 2 + 1] = d2hi;
    }
    __syncthreads();
    if (tid < 32) {
        const int m = r0 + tid;
        if (m < M_ITEMS) {
            g_a1[m] = s_red[tid * 4 + 0] + s_red[tid * 4 + 2];
            g_a2[m] = s_red[tid * 4 + 1] + s_red[tid * 4 + 3];
        }
    }
}

// ---------------------------------------------------------------------------
// K2: fused edge pass with per-block dtype sniff (int64 high-halves are 0).
// Precomputes all 640k scores with full MLP (independent edges).
// ---------------------------------------------------------------------------
__global__ void __launch_bounds__(256) k_edge(const int* __restrict__ ew,
                                              const float* __restrict__ batt) {
    __shared__ unsigned int s_or[8];
    const int e    = blockIdx.x * 256 + threadIdx.x;   // NE % 256 == 0
    const int lane = threadIdx.x & 31;

    const unsigned int odd = ((const unsigned int*)ew)[2 * e + 1];
    unsigned int v = odd;
#pragma unroll
    for (int o = 16; o; o >>= 1) v |= __shfl_xor_sync(0xFFFFFFFFu, v, o);
    if (lane == 0) s_or[threadIdx.x >> 5] = v;
    __syncthreads();
    const unsigned int t = s_or[0] | s_or[1] | s_or[2] | s_or[3] |
                           s_or[4] | s_or[5] | s_or[6] | s_or[7];
    const bool is64 = (t == 0u);

    int src, dst;
    if (is64) { src = ew[4 * e]; dst = ew[4 * e + 2]; }
    else      { src = ew[2 * e]; dst = (int)odd; }

    float att = g_a1[src] + g_a2[dst] + batt[0];
    att = att > 0.f ? att : 0.2f * att;                    // leaky_relu(0.2)
    const float sc = __expf(att - 1.0f);
    g_ds[e] = make_int2(dst, __float_as_int(sc));

    // segment boundaries (race-free: disjoint ranges per thread)
    const int sprev = (e == 0) ? -1 : (is64 ? ew[4 * e - 4] : ew[2 * e - 2]);
    if (src != sprev) {
        for (int q = sprev + 1; q <= src; ++q) g_segstart[q] = e;
    }
    if (e == NE - 1) {
        for (int q = src + 1; q <= M_ITEMS; ++q) g_segstart[q] = NE;
    }
}

// ---------------------------------------------------------------------------
// K3: warp-per-segment gather-aggregate, 16-lanes-per-edge LDG.128. (R16 form)
// 4-pair prefetch batches, launch_bounds(128,12) for 48 warps/SM.
// ---------------------------------------------------------------------------
__global__ void __launch_bounds__(128, 12) k_agg(float* __restrict__ out) {
    const int seg  = blockIdx.x * 4 + (threadIdx.x >> 5);
    const int lane = threadIdx.x & 31;
    if (seg >= M_ITEMS) return;

    const int lo = __ldg(&g_segstart[seg]);
    const int hi = __ldg(&g_segstart[seg + 1]);
    const int eh = lane >> 4;        // which edge of the pair (0/1)
    const int lq = lane & 15;        // 16B chunk within the 256B row

    const uint4* itemv = reinterpret_cast<const uint4*>(g_itemh);   // row = 16 uint4
    ull acc2[4] = {0ull, 0ull, 0ull, 0ull};
    float ssum = 0.f;

    for (int base = lo; base < hi; base += 32) {
        const int cnt = min(32, hi - base);
        int   dst = 0;
        float sc  = 0.f;
        if (lane < cnt) {
            const int2 ds = g_ds[base + lane];
            dst = ds.x;
            sc  = __int_as_float(ds.y);
        }
        ssum += sc;   // per-lane partial, fixed order

        for (int j = 0; j < cnt; j += 8) {    // 8 edges (4 pairs) per batch, zero-padded
            int d[4]; float c[4]; uint4 v[4];
#pragma unroll
            for (int u = 0; u < 4; ++u) {
                d[u] = __shfl_sync(0xFFFFFFFFu, dst, j + 2 * u + eh);  // padded -> 0
                c[u] = __shfl_sync(0xFFFFFFFFu, sc,  j + 2 * u + eh);  // padded -> 0.0
            }
#pragma unroll
            for (int u = 0; u < 4; ++u) v[u] = itemv[d[u] * 16 + lq]; // 32-bit offset
#pragma unroll
            for (int u = 0; u < 4; ++u) {
                const ull cc = pk2(c[u], c[u]);
                const uint32_t* pv = reinterpret_cast<const uint32_t*>(&v[u]);
#pragma unroll
                for (int q = 0; q < 4; ++q) {
                    const float flo = __uint_as_float(pv[q] << 16);          // exact
                    const float fhi = __uint_as_float(pv[q] & 0xffff0000u);  // exact
                    fma2(acc2[q], pk2(flo, fhi), cc);
                }
            }
        }
    }

    // unpack, combine pair halves (fixed order) + score total reduce
    float acc[8];
#pragma unroll
    for (int q = 0; q < 4; ++q) upk2(acc2[q], acc[2 * q], acc[2 * q + 1]);
#pragma unroll
    for (int q = 0; q < 8; ++q) acc[q] += __shfl_xor_sync(0xFFFFFFFFu, acc[q], 16);
#pragma unroll
    for (int o = 16; o; o >>= 1) ssum += __shfl_xor_sync(0xFFFFFFFFu, ssum, o);
    const float inv = (hi > lo) ? 1.f / ssum : 0.f;

    float4 r;
    r.x = 1.f / (1.f + __expf(-acc[eh * 4 + 0] * inv));
    r.y = 1.f / (1.f + __expf(-acc[eh * 4 + 1] * inv));
    r.z = 1.f / (1.f + __expf(-acc[eh * 4 + 2] * inv));
    r.w = 1.f / (1.f + __expf(-acc[eh * 4 + 3] * inv));
    reinterpret_cast<float4*>(out)[(size_t)seg * 32 + lq * 2 + eh] = r;
}

// ---------------------------------------------------------------------------
extern "C" void kernel_launch(void* const* d_in, const int* in_sizes, int n_in,
                              void* d_out, int out_size) {
    const float* emb  = (const float*)d_in[0];      // (20001, 128) f32
    const int*   edge = (const int*)d_in[1];        // (640000, 2) int (32/64-bit, sniffed)
    const float* W    = (const float*)d_in[2];      // (128, 128) f32
    const float* b    = (const float*)d_in[3];      // (128,) f32
    const float* Watt = (const float*)d_in[4];      // (256, 1) f32
    const float* batt = (const float*)d_in[5];      // (1,) f32
    float*       out  = (float*)d_out;              // (20001, 128) f32

    cudaFuncSetAttribute(k_gemm, cudaFuncAttributeMaxDynamicSharedMemorySize, SM_TOTAL);

    k_prep<<<8, 128>>>(W);
    k_gemm<<<(M_ITEMS + TILE_M - 1) / TILE_M, 128, SM_TOTAL>>>(emb, b, Watt);   // 626 CTAs
    k_edge<<<NE / 256, 256>>>(edge, batt);
    k_agg <<<(M_ITEMS + 3) / 4, 128>>>(out);
}